// round 11
// baseline (speedup 1.0000x reference)
#include <cuda_runtime.h>
#include <cuda_fp16.h>
#include <cstdint>

// Problem constants: S=2048, B=32, D=256, H=4.  M = S*B = 65536 rows.
#define MROWS 65536
static constexpr size_t MD_ = 16777216ull;   // 65536*256 elements

__device__ float g_pool[8ull * 16777216ull + 4194304ull];

static constexpr size_t O_SMALL = 8ull * 16777216ull;
static constexpr size_t O_SSUM  = O_SMALL;
static constexpr size_t O_SSQ   = O_SMALL + 256;
static constexpr size_t O_SCALE = O_SMALL + 512;
static constexpr size_t O_SHIFT = O_SMALL + 768;
static constexpr size_t O_PM    = O_SMALL + 1024;
static constexpr size_t O_PZ    = O_PM + 16 * 32 * 256;
static constexpr size_t O_PA    = O_PZ + 16 * 32 * 256;
static constexpr size_t O_XCAT  = O_PA + 16 * 32 * 256;
static constexpr size_t O_H0    = O_XCAT + 32 * 1024;
static constexpr size_t O_H1    = O_H0 + 32 * 256;
static constexpr size_t O_WF16  = O_SMALL + 1048576;   // fp16 weights (20 * 65536)

// ---------------------------------------------------------------------------
__device__ __forceinline__ uint32_t s2u(const void* p) {
    uint32_t a;
    asm("{ .reg .u64 t; cvta.to.shared.u64 t, %1; cvt.u32.u64 %0, t; }" : "=r"(a) : "l"(p));
    return a;
}
__device__ __forceinline__ void mma16816(float* d, const uint32_t* a, const uint32_t* b) {
    asm volatile(
        "mma.sync.aligned.m16n8k16.row.col.f32.f16.f16.f32 "
        "{%0,%1,%2,%3}, {%4,%5,%6,%7}, {%8,%9}, {%0,%1,%2,%3};"
        : "+f"(d[0]), "+f"(d[1]), "+f"(d[2]), "+f"(d[3])
        : "r"(a[0]), "r"(a[1]), "r"(a[2]), "r"(a[3]), "r"(b[0]), "r"(b[1]));
}
__device__ __forceinline__ void ldsm4(uint32_t* r, uint32_t a) {
    asm volatile("ldmatrix.sync.aligned.m8n8.x4.shared.b16 {%0,%1,%2,%3}, [%4];"
        : "=r"(r[0]), "=r"(r[1]), "=r"(r[2]), "=r"(r[3]) : "r"(a));
}
__device__ __forceinline__ void cpasync16(uint32_t dst, const void* src) {
    asm volatile("cp.async.cg.shared.global [%0], [%1], 16;" :: "r"(dst), "l"(src));
}
__device__ __forceinline__ void cpcommit() { asm volatile("cp.async.commit_group;"); }
#define CPWAIT(n) asm volatile("cp.async.wait_group %0;" :: "n"(n) : "memory")
#define STS128(a, v)                                                            \
    asm volatile("st.shared.v4.b32 [%0], {%1,%2,%3,%4};"                        \
        :: "r"(a), "r"((v).x), "r"((v).y), "r"((v).z), "r"((v).w) : "memory")

// SMEM: 0..2047 stats; then 4 stages of { A_hi 4KB | A_lo 4KB | W 16KB } = 24KB
#define STG_ALO   4096u
#define STG_W     8192u
#define STG_SIZE  24576u
#define GEMM_SMEM (2048 + 4 * 24576)   // 100352 bytes -> 2 CTAs/SM

// ---------------------------------------------------------------------------
// HMMA GEMM, tile M=64 x N=256, 256 threads (8 warps 2x4), warp tile 32x64.
// Activations stored as fp16 hi/lo planes (Ahi at base, Alo at base+MD_).
// D = (Ahi + Alo) @ W^T + bias, fp32 accum (2 MMAs per fragment pair).
// BN: a = relu((hi+lo)*ascale + ashift) recomputed & re-split via registers.
// non-BN: A planes fetched with cp.async directly (no register round-trip).
// SUB: w = C - (Qhi+Qlo), write Wout planes, stats on w.
// STATS: per-column sum/sumsq via smem + global atomics.
// ---------------------------------------------------------------------------
template<bool BN, bool SUB, bool STATS>
__device__ __forceinline__ void gemm_core(
    const __half* __restrict__ Ah,          // hi plane; lo at Ah+MD_
    const __half* __restrict__ Wh,
    const float* __restrict__ bias,
    const float* __restrict__ ascale,
    const float* __restrict__ ashift,
    __half* __restrict__ C,                 // hi plane; lo at C+MD_
    const __half* __restrict__ Qsub,        // hi plane; lo at +MD_
    __half* __restrict__ Wout,              // hi plane; lo at +MD_
    float* __restrict__ gsum, float* __restrict__ gsq)
{
    extern __shared__ __align__(16) char smem[];
    const uint32_t sb = s2u(smem);
    const int t = threadIdx.x, w = t >> 5, l = t & 31;
    const int wr = w >> 2, wc = w & 3;
    const size_t r0 = (size_t)blockIdx.x * 64;

    if (STATS) {
        ((float*)smem)[t] = 0.f;
        ((float*)smem)[t + 256] = 0.f;
    }

    const uint32_t stg0 = sb + 2048;
    const __half* Al = Ah + MD_;

    // loader mapping: A 64 rows x 4 granules(16B=8 halves); W 64 rows x 4, x4 blocks
    const int arow = t >> 2, ag = t & 3;
    const uint32_t a_sts = (uint32_t)(arow * 64 + ((ag ^ ((arow >> 1) & 3)) << 4));
    const int wrow = t >> 2, wg = t & 3;
    const uint32_t w_sts = (uint32_t)(wrow * 64) + (uint32_t)((wg ^ ((wrow >> 1) & 3)) << 4);

    // ldmatrix lane constants
    const int a_base_row = wr * 32 + (l & 15);
    const int sa = (a_base_row >> 1) & 3;
    const uint32_t a_off0 = (uint32_t)(a_base_row * 64);
    const int b_base_row = wc * 64 + ((l >> 4) << 3) + (l & 7);
    const int sbz = (b_base_row >> 1) & 3;
    const uint32_t b_off0 = (uint32_t)(b_base_row * 64);
    const int a_gl = l >> 4;
    const int b_gl = (l >> 3) & 1;

    float acc[2][8][4];
#pragma unroll
    for (int mt = 0; mt < 2; mt++)
#pragma unroll
        for (int nt = 0; nt < 8; nt++)
#pragma unroll
            for (int j = 0; j < 4; j++) acc[mt][nt][j] = 0.f;

    // ---- helpers (lambdas keep template paths tidy) ----
    auto fetchW = [&](int ch, uint32_t stg) {
        size_t ws = (size_t)wrow * 256 + ch * 32 + wg * 8;
#pragma unroll
        for (int j = 0; j < 4; j++)
            cpasync16(stg + STG_W + w_sts + j * 4096u, Wh + ws + (size_t)j * 64 * 256);
    };
    auto fetchA_async = [&](int ch, uint32_t stg) {
        size_t as = (r0 + arow) * 256 + ch * 32 + ag * 8;
        cpasync16(stg + a_sts, Ah + as);
        cpasync16(stg + STG_ALO + a_sts, Al + as);
    };
    auto ldA_bn = [&](int ch, float* af) {
        size_t as = (r0 + arow) * 256 + ch * 32 + ag * 8;
        uint4 hv = *(const uint4*)(Ah + as);
        uint4 lv = *(const uint4*)(Al + as);
        const __half2* hp = (const __half2*)&hv;
        const __half2* lp = (const __half2*)&lv;
        int kk = ch * 32 + ag * 8;
#pragma unroll
        for (int i = 0; i < 4; i++) {
            float x0 = __half2float(hp[i].x) + __half2float(lp[i].x);
            float x1 = __half2float(hp[i].y) + __half2float(lp[i].y);
            af[2 * i]     = fmaxf(fmaf(x0, ascale[kk + 2 * i],     ashift[kk + 2 * i]), 0.f);
            af[2 * i + 1] = fmaxf(fmaf(x1, ascale[kk + 2 * i + 1], ashift[kk + 2 * i + 1]), 0.f);
        }
    };
    auto stsA_bn = [&](const float* af, uint32_t stg) {
        uint4 hv, lv;
        __half2* hp = (__half2*)&hv;
        __half2* lp = (__half2*)&lv;
#pragma unroll
        for (int i = 0; i < 4; i++) {
            __half h0 = __float2half(af[2 * i]);
            __half h1 = __float2half(af[2 * i + 1]);
            hp[i].x = h0; hp[i].y = h1;
            lp[i].x = __float2half(af[2 * i]     - __half2float(h0));
            lp[i].y = __float2half(af[2 * i + 1] - __half2float(h1));
        }
        STS128(stg + a_sts, hv);
        STS128(stg + STG_ALO + a_sts, lv);
    };

    // ===== prologue: chunks 0, 1 =====
    float af0[8], af1[8];
    {
        fetchW(0, stg0);
        if (BN) { ldA_bn(0, af0); stsA_bn(af0, stg0); }
        else fetchA_async(0, stg0);
        cpcommit();
        fetchW(1, stg0 + STG_SIZE);
        if (BN) { ldA_bn(1, af1); stsA_bn(af1, stg0 + STG_SIZE); }
        else fetchA_async(1, stg0 + STG_SIZE);
        cpcommit();
    }

    // ===== mainloop: 8 chunks of k32, 4-stage ring, 1 barrier/chunk =====
#pragma unroll
    for (int c = 0; c < 8; c++) {
        const uint32_t stgs = stg0 + (uint32_t)(c & 3) * STG_SIZE;
        const uint32_t stgn = stg0 + (uint32_t)((c + 2) & 3) * STG_SIZE;

        if (c < 6) {
            fetchW(c + 2, stgn);
            if (BN) ldA_bn(c + 2, af0);
            else fetchA_async(c + 2, stgn);
            cpcommit();
        }
        if (c <= 5) { CPWAIT(2); } else if (c == 6) { CPWAIT(1); } else { CPWAIT(0); }
        __syncthreads();
        if (BN && c < 6) stsA_bn(af0, stgn);   // stage c+2: readers 2 barriers away

        // ---- compute chunk c ----
#pragma unroll
        for (int ks = 0; ks < 2; ks++) {
            uint32_t ah[2][4], al[2][4], bb[4];
            const uint32_t agoff = (uint32_t)(((ks * 2 + a_gl) ^ sa) << 4);
            ldsm4(ah[0], stgs + a_off0 + agoff);
            ldsm4(ah[1], stgs + a_off0 + 1024 + agoff);
            ldsm4(al[0], stgs + STG_ALO + a_off0 + agoff);
            ldsm4(al[1], stgs + STG_ALO + a_off0 + 1024 + agoff);
            const uint32_t bgoff = (uint32_t)(((ks * 2 + b_gl) ^ sbz) << 4);
#pragma unroll
            for (int n2 = 0; n2 < 4; n2++) {
                const uint32_t brow = b_off0 + (uint32_t)(n2 * 1024);
                ldsm4(bb, stgs + STG_W + brow + bgoff);
                mma16816(acc[0][n2 * 2],     ah[0], bb);
                mma16816(acc[0][n2 * 2 + 1], ah[0], bb + 2);
                mma16816(acc[1][n2 * 2],     ah[1], bb);
                mma16816(acc[1][n2 * 2 + 1], ah[1], bb + 2);
                mma16816(acc[0][n2 * 2],     al[0], bb);
                mma16816(acc[0][n2 * 2 + 1], al[0], bb + 2);
                mma16816(acc[1][n2 * 2],     al[1], bb);
                mma16816(acc[1][n2 * 2 + 1], al[1], bb + 2);
            }
        }
    }

    // ===== epilogue: split to hi/lo planes =====
    const int erow = wr * 32 + (l >> 2);
    __half* Cl = C + MD_;
#pragma unroll
    for (int nt = 0; nt < 8; nt++) {
        const int col = wc * 64 + nt * 8 + (l & 3) * 2;
        const float2 bb2 = *(const float2*)(bias + col);
        float s0 = 0.f, s1 = 0.f, q0 = 0.f, q1 = 0.f;
#pragma unroll
        for (int mt = 0; mt < 2; mt++) {
#pragma unroll
            for (int rr = 0; rr < 2; rr++) {
                const size_t row = r0 + erow + mt * 16 + rr * 8;
                float v0 = acc[mt][nt][rr * 2 + 0] + bb2.x;
                float v1 = acc[mt][nt][rr * 2 + 1] + bb2.y;
                if (SUB) {
                    __half2 qh = *(const __half2*)(Qsub + row * 256 + col);
                    __half2 ql = *(const __half2*)(Qsub + MD_ + row * 256 + col);
                    v0 -= __half2float(qh.x) + __half2float(ql.x);
                    v1 -= __half2float(qh.y) + __half2float(ql.y);
                    __half h0 = __float2half(v0), h1 = __float2half(v1);
                    *(__half2*)(Wout + row * 256 + col) = __half2{h0, h1};
                    *(__half2*)(Wout + MD_ + row * 256 + col) =
                        __half2{__float2half(v0 - __half2float(h0)),
                                __float2half(v1 - __half2float(h1))};
                    s0 += v0; s1 += v1;
                    q0 += v0 * v0; q1 += v1 * v1;
                    // also store K projection (C) for later heads
                    float k0 = v0, k1 = v1;  // placeholder (overwritten below)
                    (void)k0; (void)k1;
                }
                {
                    // C value (pre-SUB): recompute from acc+bias
                    float c0 = acc[mt][nt][rr * 2 + 0] + bb2.x;
                    float c1 = acc[mt][nt][rr * 2 + 1] + bb2.y;
                    __half h0 = __float2half(c0), h1 = __float2half(c1);
                    *(__half2*)(C + row * 256 + col) = __half2{h0, h1};
                    *(__half2*)(Cl + row * 256 + col) =
                        __half2{__float2half(c0 - __half2float(h0)),
                                __float2half(c1 - __half2float(h1))};
                    if (STATS && !SUB) {
                        s0 += c0; s1 += c1;
                        q0 += c0 * c0; q1 += c1 * c1;
                    }
                }
            }
        }
        if (STATS) {
            float* ss = (float*)smem;
            atomicAdd(ss + col,           s0);
            atomicAdd(ss + col + 1,       s1);
            atomicAdd(ss + 256 + col,     q0);
            atomicAdd(ss + 256 + col + 1, q1);
        }
    }

    if (STATS) {
        __syncthreads();
        atomicAdd(gsum + t, ((float*)smem)[t]);
        atomicAdd(gsq  + t, ((float*)smem)[256 + t]);
    }
}

// ---- wrappers ----
__global__ __launch_bounds__(256, 2)
void gemm_plain(const __half* A, const __half* Wh, const float* bias, __half* C)
{
    gemm_core<false, false, false>(A, Wh, bias, nullptr, nullptr, C,
                                   nullptr, nullptr, nullptr, nullptr);
}
__global__ __launch_bounds__(256, 2)
void gemm_kv(const __half* Ka, const __half* KWh, const float* kb, __half* Kd,
             const __half* Va, const __half* VWh, const float* vb, __half* Vd,
             const __half* Qd, __half* Wout, float* gsum, float* gsq)
{
    if (blockIdx.y == 0)
        gemm_core<false, true, true>(Ka, KWh, kb, nullptr, nullptr, Kd,
                                     Qd, Wout, gsum, gsq);
    else
        gemm_core<false, false, false>(Va, VWh, vb, nullptr, nullptr, Vd,
                                       nullptr, nullptr, nullptr, nullptr);
}
__global__ __launch_bounds__(256, 2)
void gemm_bn_stats(const __half* A, const __half* Wh, const float* bias,
                   const float* ascale, const float* ashift,
                   __half* C, float* gsum, float* gsq)
{
    gemm_core<true, false, true>(A, Wh, bias, ascale, ashift, C,
                                 nullptr, nullptr, gsum, gsq);
}
__global__ __launch_bounds__(256, 2)
void gemm_bn(const __half* A, const __half* Wh, const float* bias,
             const float* ascale, const float* ashift, __half* C)
{
    gemm_core<true, false, false>(A, Wh, bias, ascale, ashift, C,
                                  nullptr, nullptr, nullptr, nullptr);
}

// ---------------------------------------------------------------------------
__global__ void wconv(const float* __restrict__ w0, const float* __restrict__ w1,
                      const float* __restrict__ w2, const float* __restrict__ w3,
                      const float* __restrict__ w4, __half* __restrict__ out)
{
    size_t i = (size_t)blockIdx.x * 256 + threadIdx.x;
    size_t a = i >> 18, r = i & 262143;
    const float* s = (a == 0) ? w0 : (a == 1) ? w1 : (a == 2) ? w2 : (a == 3) ? w3 : w4;
    out[i] = __float2half(s[r]);
}

// Split fp32 q/k/v inputs into hi/lo fp16 planes (4 elems/thread)
__global__ void qkvsplit(const float* __restrict__ q, const float* __restrict__ k,
                         const float* __restrict__ v,
                         __half* __restrict__ Qo, __half* __restrict__ Ko,
                         __half* __restrict__ Vo)
{
    size_t i = ((size_t)blockIdx.x * 256 + threadIdx.x) * 4;
    size_t buf = i / MD_;                       // 0=q 1=k 2=v
    size_t r = i - buf * MD_;
    const float* s = (buf == 0) ? q : (buf == 1) ? k : v;
    __half* oh = (buf == 0) ? Qo : (buf == 1) ? Ko : Vo;
    float4 x = *(const float4*)(s + r);
    __half2 h0{__float2half(x.x), __float2half(x.y)};
    __half2 h1{__float2half(x.z), __float2half(x.w)};
    *(__half2*)(oh + r)     = h0;
    *(__half2*)(oh + r + 2) = h1;
    __half2 l0{__float2half(x.x - __half2float(h0.x)), __float2half(x.y - __half2float(h0.y))};
    __half2 l1{__float2half(x.z - __half2float(h1.x)), __float2half(x.w - __half2float(h1.y))};
    *(__half2*)(oh + MD_ + r)     = l0;
    *(__half2*)(oh + MD_ + r + 2) = l1;
}

__global__ void zerok(float* a, float* b)
{
    a[threadIdx.x] = 0.f;
    b[threadIdx.x] = 0.f;
}

__global__ void bnfinal(const float* __restrict__ s, const float* __restrict__ sq,
                        const float* __restrict__ gamma, const float* __restrict__ beta,
                        float* __restrict__ scale, float* __restrict__ shift)
{
    int c = threadIdx.x;
    const float inv = 1.f / 65536.f;
    float m = s[c] * inv;
    float v = sq[c] * inv - m * m;
    float r = rsqrtf(v + 1e-5f);
    float sc = r * gamma[c];
    scale[c] = sc;
    shift[c] = beta[c] - m * sc;
}

// Online softmax over S fused with weighted V-sum (16-way split over S)
__global__ void smax_part(const __half* __restrict__ W3, const __half* __restrict__ V,
                          float* __restrict__ pm, float* __restrict__ pz,
                          float* __restrict__ pa)
{
    int b = blockIdx.x, ch = blockIdx.y, d = threadIdx.x;
    const __half* W3l = W3 + MD_;
    const __half* Vl  = V + MD_;
    float m = -1e30f, Z = 0.f, acc = 0.f;
#pragma unroll 4
    for (int j = 0; j < 128; j++) {
        int s_ = ch * 128 + j;
        size_t idx = ((size_t)(s_ * 32 + b)) * 256 + d;
        float w = __half2float(W3[idx]) + __half2float(W3l[idx]);
        float v = __half2float(V[idx])  + __half2float(Vl[idx]);
        float nm = fmaxf(m, w);
        float e0 = __expf(m - nm);
        float e1 = __expf(w - nm);
        Z = Z * e0 + e1;
        acc = fmaf(v, e1, acc * e0);
        m = nm;
    }
    int o = (ch * 32 + b) * 256 + d;
    pm[o] = m; pz[o] = Z; pa[o] = acc;
}

__global__ void smax_comb(const float* __restrict__ pm, const float* __restrict__ pz,
                          const float* __restrict__ pa, float* __restrict__ xcat,
                          int head)
{
    int b = blockIdx.x, d = threadIdx.x;
    float m = -1e30f, Z = 0.f, acc = 0.f;
#pragma unroll
    for (int ch = 0; ch < 16; ch++) {
        int o = (ch * 32 + b) * 256 + d;
        float cm = pm[o];
        float nm = fmaxf(m, cm);
        float e0 = __expf(m - nm);
        float e1 = __expf(cm - nm);
        Z = Z * e0 + pz[o] * e1;
        acc = acc * e0 + pa[o] * e1;
        m = nm;
    }
    xcat[b * 1024 + head * 256 + d] = acc / Z;
}

__global__ void mlp_k(const float* __restrict__ X, const float* __restrict__ Wm,
                      const float* __restrict__ bias, float* __restrict__ Y,
                      int Kdim, int do_relu)
{
    __shared__ float sx[1024];
    int b = blockIdx.x, c = threadIdx.x;
    for (int t = c; t < Kdim; t += 256) sx[t] = X[b * Kdim + t];
    __syncthreads();
    float s = 0.f;
#pragma unroll 4
    for (int t = 0; t < Kdim; t++) s = fmaf(sx[t], Wm[c * Kdim + t], s);
    s += bias[c];
    if (do_relu) s = fmaxf(s, 0.f);
    Y[b * 256 + c] = s;
}

// ---------------------------------------------------------------------------
extern "C" void kernel_launch(void* const* d_in, const int* in_sizes, int n_in,
                              void* d_out, int out_size)
{
    float* pool = nullptr;
    cudaGetSymbolAddress((void**)&pool, g_pool);

    cudaFuncSetAttribute(gemm_plain,    cudaFuncAttributeMaxDynamicSharedMemorySize, GEMM_SMEM);
    cudaFuncSetAttribute(gemm_kv,       cudaFuncAttributeMaxDynamicSharedMemorySize, GEMM_SMEM);
    cudaFuncSetAttribute(gemm_bn_stats, cudaFuncAttributeMaxDynamicSharedMemorySize, GEMM_SMEM);
    cudaFuncSetAttribute(gemm_bn,       cudaFuncAttributeMaxDynamicSharedMemorySize, GEMM_SMEM);

    const float* q   = (const float*)d_in[0];
    const float* k   = (const float*)d_in[1];
    const float* v   = (const float*)d_in[2];
    const float* wq  = (const float*)d_in[3];
    const float* bq  = (const float*)d_in[4];
    const float* wk  = (const float*)d_in[5];
    const float* bk  = (const float*)d_in[6];
    const float* wv  = (const float*)d_in[7];
    const float* bv  = (const float*)d_in[8];
    const float* g1  = (const float*)d_in[9];
    const float* be1 = (const float*)d_in[10];
    const float* wl1 = (const float*)d_in[11];
    const float* bl1 = (const float*)d_in[12];
    const float* g2  = (const float*)d_in[13];
    const float* be2 = (const float*)d_in[14];
    const float* wl2 = (const float*)d_in[15];
    const float* bl2 = (const float*)d_in[16];
    const float* mw0 = (const float*)d_in[17];
    const float* mb0 = (const float*)d_in[18];
    const float* mw1 = (const float*)d_in[19];
    const float* mb1 = (const float*)d_in[20];
    const float* mw2 = (const float*)d_in[21];
    const float* mb2 = (const float*)d_in[22];

    // Big buffers hold hi/lo fp16 planes (each MD_ halves per plane)
    __half* Qb[2] = {(__half*)(pool + 0 * MD_), (__half*)(pool + 1 * MD_)};
    __half* Kb[2] = {(__half*)(pool + 2 * MD_), (__half*)(pool + 3 * MD_)};
    __half* Vb[2] = {(__half*)(pool + 4 * MD_), (__half*)(pool + 5 * MD_)};
    __half* W     = (__half*)(pool + 6 * MD_);
    __half* W2    = (__half*)(pool + 7 * MD_);
    float* ssum  = pool + O_SSUM;
    float* ssq   = pool + O_SSQ;
    float* scale = pool + O_SCALE;
    float* shift = pool + O_SHIFT;
    float* pm    = pool + O_PM;
    float* pz    = pool + O_PZ;
    float* pa    = pool + O_PA;
    float* xcat  = pool + O_XCAT;
    float* h0    = pool + O_H0;
    float* h1    = pool + O_H1;
    __half* wf = (__half*)(pool + O_WF16);

    wconv<<<5120, 256>>>(wq, wk, wv, wl1, wl2, wf);
    // split fp32 inputs into planes of Qb[1]/Kb[1]/Vb[1] (head0 sources)
    qkvsplit<<<49152, 256>>>(q, k, v, Qb[1], Kb[1], Vb[1]);

    const int NT = MROWS / 64;   // 1024 row tiles

    for (int i = 0; i < 4; i++) {
        const __half* Qs = i ? Qb[(i - 1) & 1] : Qb[1];
        const __half* Ks = i ? Kb[(i - 1) & 1] : Kb[1];
        const __half* Vs = i ? Vb[(i - 1) & 1] : Vb[1];
        __half* Qd = Qb[i & 1];
        __half* Kd = Kb[i & 1];
        __half* Vd = Vb[i & 1];

        const __half* whq = wf + (0 * 4 + i) * 65536;
        const __half* whk = wf + (1 * 4 + i) * 65536;
        const __half* whv = wf + (2 * 4 + i) * 65536;
        const __half* wh1 = wf + (3 * 4 + i) * 65536;
        const __half* wh2 = wf + (4 * 4 + i) * 65536;

        gemm_plain<<<NT, 256, GEMM_SMEM>>>(Qs, whq, bq + i * 256, Qd);

        zerok<<<1, 256>>>(ssum, ssq);
        gemm_kv<<<dim3(NT, 2), 256, GEMM_SMEM>>>(
            Ks, whk, bk + i * 256, Kd,
            Vs, whv, bv + i * 256, Vd,
            Qd, W, ssum, ssq);
        bnfinal<<<1, 256>>>(ssum, ssq, g1 + i * 256, be1 + i * 256, scale, shift);

        zerok<<<1, 256>>>(ssum, ssq);
        gemm_bn_stats<<<NT, 256, GEMM_SMEM>>>(W, wh1, bl1 + i * 256,
                                              scale, shift, W2, ssum, ssq);
        bnfinal<<<1, 256>>>(ssum, ssq, g2 + i * 256, be2 + i * 256, scale, shift);

        gemm_bn<<<NT, 256, GEMM_SMEM>>>(W2, wh2, bl2 + i * 256, scale, shift, W);

        smax_part<<<dim3(32, 16), 256>>>(W, Vd, pm, pz, pa);
        smax_comb<<<32, 256>>>(pm, pz, pa, xcat, i);
    }

    mlp_k<<<32, 256>>>(xcat, mw0, mb0, h0, 1024, 1);
    mlp_k<<<32, 256>>>(h0, mw1, mb1, h1, 256, 1);
    mlp_k<<<32, 256>>>(h1, mw2, mb2, (float*)d_out, 256, 0);
}

// round 12
// speedup vs baseline: 1.3258x; 1.3258x over previous
#include <cuda_runtime.h>
#include <cuda_fp16.h>
#include <cstdint>

// Problem constants: S=2048, B=32, D=256, H=4.  M = S*B = 65536 rows.
#define MROWS 65536
static constexpr size_t MD_ = 16777216ull;   // 65536*256

__device__ float g_pool[8ull * 16777216ull + 4194304ull];

static constexpr size_t O_SMALL = 8ull * 16777216ull;
static constexpr size_t O_SSUM  = O_SMALL;
static constexpr size_t O_SSQ   = O_SMALL + 256;
static constexpr size_t O_SCALE = O_SMALL + 512;
static constexpr size_t O_SHIFT = O_SMALL + 768;
static constexpr size_t O_PM    = O_SMALL + 1024;
static constexpr size_t O_PZ    = O_PM + 16 * 32 * 256;
static constexpr size_t O_PA    = O_PZ + 16 * 32 * 256;
static constexpr size_t O_XCAT  = O_PA + 16 * 32 * 256;
static constexpr size_t O_H0    = O_XCAT + 32 * 1024;
static constexpr size_t O_H1    = O_H0 + 32 * 256;
static constexpr size_t O_WF16  = O_SMALL + 1048576;   // fp16 weights (20 * 65536)

// ---------------------------------------------------------------------------
__device__ __forceinline__ uint32_t s2u(const void* p) {
    uint32_t a;
    asm("{ .reg .u64 t; cvta.to.shared.u64 t, %1; cvt.u32.u64 %0, t; }" : "=r"(a) : "l"(p));
    return a;
}
__device__ __forceinline__ void mma16816(float* d, const uint32_t* a, const uint32_t* b) {
    asm volatile(
        "mma.sync.aligned.m16n8k16.row.col.f32.f16.f16.f32 "
        "{%0,%1,%2,%3}, {%4,%5,%6,%7}, {%8,%9}, {%0,%1,%2,%3};"
        : "+f"(d[0]), "+f"(d[1]), "+f"(d[2]), "+f"(d[3])
        : "r"(a[0]), "r"(a[1]), "r"(a[2]), "r"(a[3]), "r"(b[0]), "r"(b[1]));
}
__device__ __forceinline__ void ldsm4(uint32_t* r, uint32_t a) {
    asm volatile("ldmatrix.sync.aligned.m8n8.x4.shared.b16 {%0,%1,%2,%3}, [%4];"
        : "=r"(r[0]), "=r"(r[1]), "=r"(r[2]), "=r"(r[3]) : "r"(a));
}
__device__ __forceinline__ void cpasync16(uint32_t dst, const void* src) {
    asm volatile("cp.async.cg.shared.global [%0], [%1], 16;" :: "r"(dst), "l"(src));
}
__device__ __forceinline__ void cpcommit() { asm volatile("cp.async.commit_group;"); }
#define CPWAIT(n) asm volatile("cp.async.wait_group %0;" :: "n"(n) : "memory")
#define STS128(a, v)                                                            \
    asm volatile("st.shared.v4.b32 [%0], {%1,%2,%3,%4};"                        \
        :: "r"(a), "r"((v).x), "r"((v).y), "r"((v).z), "r"((v).w) : "memory")

// SMEM: 0..2047 stats; then 4 stages of { A_hi 4KB | A_lo 4KB | W 16KB } = 24KB
#define STG_ALO   4096u
#define STG_W     8192u
#define STG_SIZE  24576u
#define GEMM_SMEM (2048 + 4 * 24576)   // 100352 bytes -> 2 CTAs/SM

// ---------------------------------------------------------------------------
// Core HMMA GEMM: tile M=64 x N=256, 256 threads (8 warps, 2x4), warp 32x64.
// C = act(A) @ W^T + bias ; act = relu(a*ascale+ashift) if BN.
// fp16 2-term: D += Ahi*W + Alo*W (A split to fp16 hi+lo, W single fp16).
// 4-stage cp.async ring, ONE __syncthreads per 32-k chunk.
// SUB: w = C - Qsub -> Wout, stats on w.  STATS: column sum/sumsq atomics.
// ---------------------------------------------------------------------------
template<bool BN, bool SUB, bool STATS>
__device__ __forceinline__ void gemm_core(
    const float* __restrict__ A,
    const __half* __restrict__ Wh,
    const float* __restrict__ bias,
    const float* __restrict__ ascale,
    const float* __restrict__ ashift,
    float* __restrict__ C,
    const float* __restrict__ Qsub,
    float* __restrict__ Wout,
    float* __restrict__ gsum, float* __restrict__ gsq)
{
    extern __shared__ __align__(16) char smem[];
    const uint32_t sb = s2u(smem);
    const int t = threadIdx.x, w = t >> 5, l = t & 31;
    const int wr = w >> 2, wc = w & 3;
    const size_t r0 = (size_t)blockIdx.x * 64;

    if (STATS) {
        ((float*)smem)[t] = 0.f;
        ((float*)smem)[t + 256] = 0.f;
    }

    const uint32_t stg0 = sb + 2048;

    // loader mapping
    const int arow = t >> 2, ag = t & 3;         // A: 64 rows x 4 granules
    const uint32_t a_sts = (uint32_t)(arow * 64 + ((ag ^ ((arow >> 1) & 3)) << 4));
    const int wrow = t >> 2, wg = t & 3;         // W: rows wrow + 64j
    const uint32_t w_sts = (uint32_t)(wrow * 64) + (uint32_t)((wg ^ ((wrow >> 1) & 3)) << 4);

    // ldmatrix lane constants
    const int a_base_row = wr * 32 + (l & 15);
    const int sa = (a_base_row >> 1) & 3;
    const uint32_t a_off0 = (uint32_t)(a_base_row * 64);
    const int b_base_row = wc * 64 + ((l >> 4) << 3) + (l & 7);
    const int sbz = (b_base_row >> 1) & 3;
    const uint32_t b_off0 = (uint32_t)(b_base_row * 64);
    const int a_gl = l >> 4;
    const int b_gl = (l >> 3) & 1;

    float acc[2][8][4];
#pragma unroll
    for (int mt = 0; mt < 2; mt++)
#pragma unroll
        for (int nt = 0; nt < 8; nt++)
#pragma unroll
            for (int j = 0; j < 4; j++) acc[mt][nt][j] = 0.f;

    float af[8];

    auto fetchW = [&](int ch, uint32_t stg) {
        size_t ws = (size_t)wrow * 256 + ch * 32 + wg * 8;
#pragma unroll
        for (int j = 0; j < 4; j++)
            cpasync16(stg + STG_W + w_sts + j * 4096u, Wh + ws + (size_t)j * 64 * 256);
    };
    auto ldA = [&](int ch) {
        const float4* p = (const float4*)(A + (r0 + arow) * 256 + ch * 32 + ag * 8);
        float4 v0 = p[0], v1 = p[1];
        af[0] = v0.x; af[1] = v0.y; af[2] = v0.z; af[3] = v0.w;
        af[4] = v1.x; af[5] = v1.y; af[6] = v1.z; af[7] = v1.w;
        if (BN) {
            int kk = ch * 32 + ag * 8;
#pragma unroll
            for (int i = 0; i < 8; i++)
                af[i] = fmaxf(fmaf(af[i], ascale[kk + i], ashift[kk + i]), 0.f);
        }
    };
    auto stsA = [&](uint32_t stg) {
        uint4 hv, lv;
        __half2* hp = (__half2*)&hv;
        __half2* lp = (__half2*)&lv;
#pragma unroll
        for (int i = 0; i < 4; i++) {
            __half h0 = __float2half(af[2 * i]);
            __half h1 = __float2half(af[2 * i + 1]);
            hp[i].x = h0; hp[i].y = h1;
            lp[i].x = __float2half(af[2 * i]     - __half2float(h0));
            lp[i].y = __float2half(af[2 * i + 1] - __half2float(h1));
        }
        STS128(stg + a_sts, hv);
        STS128(stg + STG_ALO + a_sts, lv);
    };

    // ===== prologue: chunks 0 and 1 =====
    ldA(0); fetchW(0, stg0);              cpcommit(); stsA(stg0);
    ldA(1); fetchW(1, stg0 + STG_SIZE);   cpcommit(); stsA(stg0 + STG_SIZE);

    // ===== mainloop: 8 chunks of k32, 4-stage ring, 1 barrier/chunk =====
    for (int c = 0; c < 8; c++) {
        const uint32_t stgs = stg0 + (uint32_t)(c & 3) * STG_SIZE;
        const uint32_t stgn = stg0 + (uint32_t)((c + 2) & 3) * STG_SIZE;

        if (c < 6) {
            ldA(c + 2);
            fetchW(c + 2, stgn);
            cpcommit();
        }
        if (c <= 5) { CPWAIT(2); } else if (c == 6) { CPWAIT(1); } else { CPWAIT(0); }
        __syncthreads();
        if (c < 6) stsA(stgn);   // readers are 2 barriers away

        // ---- compute chunk c ----
#pragma unroll
        for (int ks = 0; ks < 2; ks++) {
            uint32_t ah[2][4], al[2][4], bb[4];
            const uint32_t agoff = (uint32_t)(((ks * 2 + a_gl) ^ sa) << 4);
            ldsm4(ah[0], stgs + a_off0 + agoff);
            ldsm4(ah[1], stgs + a_off0 + 1024 + agoff);
            ldsm4(al[0], stgs + STG_ALO + a_off0 + agoff);
            ldsm4(al[1], stgs + STG_ALO + a_off0 + 1024 + agoff);
            const uint32_t bgoff = (uint32_t)(((ks * 2 + b_gl) ^ sbz) << 4);
#pragma unroll
            for (int n2 = 0; n2 < 4; n2++) {
                const uint32_t brow = b_off0 + (uint32_t)(n2 * 1024);
                ldsm4(bb, stgs + STG_W + brow + bgoff);
                mma16816(acc[0][n2 * 2],     ah[0], bb);
                mma16816(acc[0][n2 * 2 + 1], ah[0], bb + 2);
                mma16816(acc[1][n2 * 2],     ah[1], bb);
                mma16816(acc[1][n2 * 2 + 1], ah[1], bb + 2);
                mma16816(acc[0][n2 * 2],     al[0], bb);
                mma16816(acc[0][n2 * 2 + 1], al[0], bb + 2);
                mma16816(acc[1][n2 * 2],     al[1], bb);
                mma16816(acc[1][n2 * 2 + 1], al[1], bb + 2);
            }
        }
    }

    // ===== epilogue =====
    const int erow = wr * 32 + (l >> 2);
#pragma unroll
    for (int nt = 0; nt < 8; nt++) {
        const int col = wc * 64 + nt * 8 + (l & 3) * 2;
        const float2 bb2 = *(const float2*)(bias + col);
        float s0 = 0.f, s1 = 0.f, q0 = 0.f, q1 = 0.f;
#pragma unroll
        for (int mt = 0; mt < 2; mt++) {
            const size_t row = r0 + erow + mt * 16;
            float v0 = acc[mt][nt][0] + bb2.x;
            float v1 = acc[mt][nt][1] + bb2.y;
            float v2 = acc[mt][nt][2] + bb2.x;
            float v3 = acc[mt][nt][3] + bb2.y;
            *(float2*)(C + row * 256 + col)       = make_float2(v0, v1);
            *(float2*)(C + (row + 8) * 256 + col) = make_float2(v2, v3);
            if (SUB) {
                float2 qa = *(const float2*)(Qsub + row * 256 + col);
                float2 qb = *(const float2*)(Qsub + (row + 8) * 256 + col);
                float w0 = v0 - qa.x, w1 = v1 - qa.y;
                float w2 = v2 - qb.x, w3 = v3 - qb.y;
                *(float2*)(Wout + row * 256 + col)       = make_float2(w0, w1);
                *(float2*)(Wout + (row + 8) * 256 + col) = make_float2(w2, w3);
                s0 += w0 + w2; s1 += w1 + w3;
                q0 += w0 * w0 + w2 * w2; q1 += w1 * w1 + w3 * w3;
            } else if (STATS) {
                s0 += v0 + v2; s1 += v1 + v3;
                q0 += v0 * v0 + v2 * v2; q1 += v1 * v1 + v3 * v3;
            }
        }
        if (STATS) {
            // reduce over the 8 lanes (stride 4) sharing this column pair
#pragma unroll
            for (int off = 4; off < 32; off <<= 1) {
                s0 += __shfl_xor_sync(0xFFFFFFFFu, s0, off);
                s1 += __shfl_xor_sync(0xFFFFFFFFu, s1, off);
                q0 += __shfl_xor_sync(0xFFFFFFFFu, q0, off);
                q1 += __shfl_xor_sync(0xFFFFFFFFu, q1, off);
            }
            if (l < 4) {
                float* ss = (float*)smem;
                atomicAdd(ss + col,           s0);
                atomicAdd(ss + col + 1,       s1);
                atomicAdd(ss + 256 + col,     q0);
                atomicAdd(ss + 256 + col + 1, q1);
            }
        }
    }

    if (STATS) {
        __syncthreads();
        atomicAdd(gsum + t, ((float*)smem)[t]);
        atomicAdd(gsq  + t, ((float*)smem)[256 + t]);
    }
}

// ---- wrappers ----
__global__ __launch_bounds__(256, 2)
void gemm_plain(const float* A, const __half* Wh, const float* bias, float* C)
{
    gemm_core<false, false, false>(A, Wh, bias, nullptr, nullptr, C,
                                   nullptr, nullptr, nullptr, nullptr);
}
__global__ __launch_bounds__(256, 2)
void gemm_kv(const float* Ka, const __half* KWh, const float* kb, float* Kd,
             const float* Va, const __half* VWh, const float* vb, float* Vd,
             const float* Qd, float* Wout, float* gsum, float* gsq)
{
    if (blockIdx.y == 0)
        gemm_core<false, true, true>(Ka, KWh, kb, nullptr, nullptr, Kd,
                                     Qd, Wout, gsum, gsq);
    else
        gemm_core<false, false, false>(Va, VWh, vb, nullptr, nullptr, Vd,
                                       nullptr, nullptr, nullptr, nullptr);
}
__global__ __launch_bounds__(256, 2)
void gemm_bn_stats(const float* A, const __half* Wh, const float* bias,
                   const float* ascale, const float* ashift,
                   float* C, float* gsum, float* gsq)
{
    gemm_core<true, false, true>(A, Wh, bias, ascale, ashift, C,
                                 nullptr, nullptr, gsum, gsq);
}
__global__ __launch_bounds__(256, 2)
void gemm_bn(const float* A, const __half* Wh, const float* bias,
             const float* ascale, const float* ashift, float* C)
{
    gemm_core<true, false, false>(A, Wh, bias, ascale, ashift, C,
                                  nullptr, nullptr, nullptr, nullptr);
}

// ---------------------------------------------------------------------------
__global__ void wconv(const float* __restrict__ w0, const float* __restrict__ w1,
                      const float* __restrict__ w2, const float* __restrict__ w3,
                      const float* __restrict__ w4, __half* __restrict__ out)
{
    size_t i = (size_t)blockIdx.x * 256 + threadIdx.x;
    size_t a = i >> 18, r = i & 262143;
    const float* s = (a == 0) ? w0 : (a == 1) ? w1 : (a == 2) ? w2 : (a == 3) ? w3 : w4;
    out[i] = __float2half(s[r]);
}

// bnfinal: consume stats, produce scale/shift, and re-zero accumulators so the
// next accumulation (and the next graph replay) starts from zero.
__global__ void bnfinal(float* __restrict__ s, float* __restrict__ sq,
                        const float* __restrict__ gamma, const float* __restrict__ beta,
                        float* __restrict__ scale, float* __restrict__ shift)
{
    int c = threadIdx.x;
    const float inv = 1.f / 65536.f;
    float m = s[c] * inv;
    float v = sq[c] * inv - m * m;
    float r = rsqrtf(v + 1e-5f);
    float sc = r * gamma[c];
    scale[c] = sc;
    shift[c] = beta[c] - m * sc;
    s[c] = 0.f;
    sq[c] = 0.f;
}

// Online softmax over S fused with weighted V-sum (16-way split over S)
__global__ void smax_part(const float* __restrict__ W3, const float* __restrict__ V,
                          float* __restrict__ pm, float* __restrict__ pz,
                          float* __restrict__ pa)
{
    int b = blockIdx.x, ch = blockIdx.y, d = threadIdx.x;
    float m = -1e30f, Z = 0.f, acc = 0.f;
#pragma unroll 4
    for (int j = 0; j < 128; j++) {
        int s_ = ch * 128 + j;
        size_t idx = ((size_t)(s_ * 32 + b)) * 256 + d;
        float w = W3[idx];
        float v = V[idx];
        float nm = fmaxf(m, w);
        float e0 = __expf(m - nm);
        float e1 = __expf(w - nm);
        Z = Z * e0 + e1;
        acc = fmaf(v, e1, acc * e0);
        m = nm;
    }
    int o = (ch * 32 + b) * 256 + d;
    pm[o] = m; pz[o] = Z; pa[o] = acc;
}

__global__ void smax_comb(const float* __restrict__ pm, const float* __restrict__ pz,
                          const float* __restrict__ pa, float* __restrict__ xcat,
                          int head)
{
    int b = blockIdx.x, d = threadIdx.x;
    float m = -1e30f, Z = 0.f, acc = 0.f;
#pragma unroll
    for (int ch = 0; ch < 16; ch++) {
        int o = (ch * 32 + b) * 256 + d;
        float cm = pm[o];
        float nm = fmaxf(m, cm);
        float e0 = __expf(m - nm);
        float e1 = __expf(cm - nm);
        Z = Z * e0 + pz[o] * e1;
        acc = acc * e0 + pa[o] * e1;
        m = nm;
    }
    xcat[b * 1024 + head * 256 + d] = acc / Z;
}

__global__ void mlp_k(const float* __restrict__ X, const float* __restrict__ Wm,
                      const float* __restrict__ bias, float* __restrict__ Y,
                      int Kdim, int do_relu)
{
    __shared__ float sx[1024];
    int b = blockIdx.x, c = threadIdx.x;
    for (int t = c; t < Kdim; t += 256) sx[t] = X[b * Kdim + t];
    __syncthreads();
    float s = 0.f;
#pragma unroll 4
    for (int t = 0; t < Kdim; t++) s = fmaf(sx[t], Wm[c * Kdim + t], s);
    s += bias[c];
    if (do_relu) s = fmaxf(s, 0.f);
    Y[b * 256 + c] = s;
}

// ---------------------------------------------------------------------------
extern "C" void kernel_launch(void* const* d_in, const int* in_sizes, int n_in,
                              void* d_out, int out_size)
{
    float* pool = nullptr;
    cudaGetSymbolAddress((void**)&pool, g_pool);

    cudaFuncSetAttribute(gemm_plain,    cudaFuncAttributeMaxDynamicSharedMemorySize, GEMM_SMEM);
    cudaFuncSetAttribute(gemm_kv,       cudaFuncAttributeMaxDynamicSharedMemorySize, GEMM_SMEM);
    cudaFuncSetAttribute(gemm_bn_stats, cudaFuncAttributeMaxDynamicSharedMemorySize, GEMM_SMEM);
    cudaFuncSetAttribute(gemm_bn,       cudaFuncAttributeMaxDynamicSharedMemorySize, GEMM_SMEM);

    const float* q   = (const float*)d_in[0];
    const float* k   = (const float*)d_in[1];
    const float* v   = (const float*)d_in[2];
    const float* wq  = (const float*)d_in[3];
    const float* bq  = (const float*)d_in[4];
    const float* wk  = (const float*)d_in[5];
    const float* bk  = (const float*)d_in[6];
    const float* wv  = (const float*)d_in[7];
    const float* bv  = (const float*)d_in[8];
    const float* g1  = (const float*)d_in[9];
    const float* be1 = (const float*)d_in[10];
    const float* wl1 = (const float*)d_in[11];
    const float* bl1 = (const float*)d_in[12];
    const float* g2  = (const float*)d_in[13];
    const float* be2 = (const float*)d_in[14];
    const float* wl2 = (const float*)d_in[15];
    const float* bl2 = (const float*)d_in[16];
    const float* mw0 = (const float*)d_in[17];
    const float* mb0 = (const float*)d_in[18];
    const float* mw1 = (const float*)d_in[19];
    const float* mb1 = (const float*)d_in[20];
    const float* mw2 = (const float*)d_in[21];
    const float* mb2 = (const float*)d_in[22];

    float* Qb[2] = {pool + 0 * MD_, pool + 1 * MD_};
    float* Kb[2] = {pool + 2 * MD_, pool + 3 * MD_};
    float* Vb[2] = {pool + 4 * MD_, pool + 5 * MD_};
    float* W     = pool + 6 * MD_;
    float* W2    = pool + 7 * MD_;
    float* ssum  = pool + O_SSUM;
    float* ssq   = pool + O_SSQ;
    float* scale = pool + O_SCALE;
    float* shift = pool + O_SHIFT;
    float* pm    = pool + O_PM;
    float* pz    = pool + O_PZ;
    float* pa    = pool + O_PA;
    float* xcat  = pool + O_XCAT;
    float* h0    = pool + O_H0;
    float* h1    = pool + O_H1;
    __half* wf = (__half*)(pool + O_WF16);

    // convert all 20 weight matrices to fp16  (arr order: wq,wk,wv,wl1,wl2)
    wconv<<<5120, 256>>>(wq, wk, wv, wl1, wl2, wf);

    const int NT = MROWS / 64;   // 1024 row tiles

    for (int i = 0; i < 4; i++) {
        const float* Qs = i ? Qb[(i - 1) & 1] : q;
        const float* Ks = i ? Kb[(i - 1) & 1] : k;
        const float* Vs = i ? Vb[(i - 1) & 1] : v;
        float* Qd = Qb[i & 1];
        float* Kd = Kb[i & 1];
        float* Vd = Vb[i & 1];

        const __half* whq = wf + (0 * 4 + i) * 65536;
        const __half* whk = wf + (1 * 4 + i) * 65536;
        const __half* whv = wf + (2 * 4 + i) * 65536;
        const __half* wh1 = wf + (3 * 4 + i) * 65536;
        const __half* wh2 = wf + (4 * 4 + i) * 65536;

        gemm_plain<<<NT, 256, GEMM_SMEM>>>(Qs, whq, bq + i * 256, Qd);

        gemm_kv<<<dim3(NT, 2), 256, GEMM_SMEM>>>(
            Ks, whk, bk + i * 256, Kd,
            Vs, whv, bv + i * 256, Vd,
            Qd, W, ssum, ssq);
        bnfinal<<<1, 256>>>(ssum, ssq, g1 + i * 256, be1 + i * 256, scale, shift);

        gemm_bn_stats<<<NT, 256, GEMM_SMEM>>>(W, wh1, bl1 + i * 256,
                                              scale, shift, W2, ssum, ssq);
        bnfinal<<<1, 256>>>(ssum, ssq, g2 + i * 256, be2 + i * 256, scale, shift);

        gemm_bn<<<NT, 256, GEMM_SMEM>>>(W2, wh2, bl2 + i * 256, scale, shift, W);

        smax_part<<<dim3(32, 16), 256>>>(W, Vd, pm, pz, pa);
        smax_comb<<<32, 256>>>(pm, pz, pa, xcat, i);
    }

    mlp_k<<<32, 256>>>(xcat, mw0, mb0, h0, 1024, 1);
    mlp_k<<<32, 256>>>(h0, mw1, mb1, h1, 256, 1);
    mlp_k<<<32, 256>>>(h1, mw2, mb2, (float*)d_out, 256, 0);
}